// round 5
// baseline (speedup 1.0000x reference)
#include <cuda_runtime.h>
#include <cuda_bf16.h>
#include <cuda_fp16.h>
#include <cstdint>
#include <cstdio>

// ---------------------------------------------------------------------------
// Problem constants
// ---------------------------------------------------------------------------
#define D_MODEL   2048
#define NUM_HEADS 16
#define HEAD_DIM  128
#define BATCH     4
#define TQ        1024
#define CACHE_LEN 1024
#define M_ROWS    (BATCH * TQ)          // 4096

// scratch (device globals: allocation-free scratch per harness rules)
__device__ float  g_Q[BATCH * TQ * D_MODEL];
__device__ float  g_K[BATCH * TQ * D_MODEL];
__device__ float  g_V[BATCH * TQ * D_MODEL];
__device__ __half g_O[BATCH * TQ * D_MODEL];          // attention out, fp16 (feeds O-proj)
// fp16 copies of GEMM inputs (rounded once; GEMM hot loop does no cvt)
__device__ __half g_hq[BATCH * TQ * D_MODEL];
__device__ __half g_hk[BATCH * TQ * D_MODEL];
__device__ __half g_hv[BATCH * TQ * D_MODEL];
__device__ __half g_hWq[D_MODEL * D_MODEL];
__device__ __half g_hWk[D_MODEL * D_MODEL];
__device__ __half g_hWv[D_MODEL * D_MODEL];
__device__ __half g_hWo[D_MODEL * D_MODEL];

// ---------------------------------------------------------------------------
// helpers
// ---------------------------------------------------------------------------
__device__ __forceinline__ uint32_t f2tf(float x) {
    uint32_t u;
    asm("cvt.rna.tf32.f32 %0, %1;" : "=r"(u) : "f"(x));
    return u;
}

__device__ __forceinline__ uint32_t smem_u32(const void* p) {
    uint32_t a;
    asm("{ .reg .u64 t; cvta.to.shared.u64 t, %1; cvt.u32.u64 %0, t; }"
        : "=r"(a) : "l"(p));
    return a;
}

// fp16 m16n8k16: D += A*B  (row.col, f32 accum)
__device__ __forceinline__ void mma_f16(float* d, const uint32_t* a, const uint32_t* b) {
    asm volatile(
        "mma.sync.aligned.m16n8k16.row.col.f32.f16.f16.f32 "
        "{%0,%1,%2,%3}, {%4,%5,%6,%7}, {%8,%9}, {%0,%1,%2,%3};\n"
        : "+f"(d[0]), "+f"(d[1]), "+f"(d[2]), "+f"(d[3])
        : "r"(a[0]), "r"(a[1]), "r"(a[2]), "r"(a[3]),
          "r"(b[0]), "r"(b[1]));
}

// tf32 m16n8k8 (attention kernel, unchanged)
__device__ __forceinline__ void mma_tf32(float* d, const uint32_t* a, const uint32_t* b) {
    asm volatile(
        "mma.sync.aligned.m16n8k8.row.col.f32.tf32.tf32.f32 "
        "{%0,%1,%2,%3}, {%4,%5,%6,%7}, {%8,%9}, {%0,%1,%2,%3};\n"
        : "+f"(d[0]), "+f"(d[1]), "+f"(d[2]), "+f"(d[3])
        : "r"(a[0]), "r"(a[1]), "r"(a[2]), "r"(a[3]),
          "r"(b[0]), "r"(b[1]));
}

__device__ __forceinline__ void ldsm_x4(uint32_t* r, uint32_t addr) {
    asm volatile("ldmatrix.sync.aligned.m8n8.x4.shared.b16 {%0,%1,%2,%3}, [%4];"
                 : "=r"(r[0]), "=r"(r[1]), "=r"(r[2]), "=r"(r[3]) : "r"(addr));
}

__device__ __forceinline__ void cp_async16(uint32_t dst, const void* src) {
    asm volatile("cp.async.cg.shared.global [%0], [%1], 16;"
                 :: "r"(dst), "l"(src));
}
#define CP_COMMIT()  asm volatile("cp.async.commit_group;" ::: "memory")
#define CP_WAIT(N)   asm volatile("cp.async.wait_group %0;" :: "n"(N) : "memory")

// ---------------------------------------------------------------------------
// pre-rounding pass: dst = fp16(src) for 7 tensors in one launch (grid.z)
// ---------------------------------------------------------------------------
struct RoundArgs {
    const float* src[7];
    __half*      dst[7];
    int          n4[7];     // number of float4 elements
};

__global__ __launch_bounds__(256) void round_f16(RoundArgs ra) {
    const int z = blockIdx.z;
    const int i = blockIdx.x * 256 + threadIdx.x;
    if (i >= ra.n4[z]) return;
    float4 v = ((const float4*)ra.src[z])[i];
    __half2 h0 = __floats2half2_rn(v.x, v.y);
    __half2 h1 = __floats2half2_rn(v.z, v.w);
    uint2 u;
    u.x = *(uint32_t*)&h0;
    u.y = *(uint32_t*)&h1;
    ((uint2*)ra.dst[z])[i] = u;
}

// ---------------------------------------------------------------------------
// Pipelined TN GEMM (fp16 HMMA):  C[M,N] = A[M,K] * W[N,K]^T + bias[N]
// CTA tile 128x256, warp tile 64x64 (8 warps, 2x4), K-tile 64 (128B rows),
// 3-stage cp.async ring (144KB, 1 CTA/SM), ldmatrix frags, m16n8k16 HMMA.
// Per warp per k16-step: 8 LDSM -> 32 HMMA (4.0 HMMA/LDSM duty ratio).
// SMEM row = 64 halves = 128B, swizzle: byte_off ^ ((row&7)<<4).
// ---------------------------------------------------------------------------
#define NST        3
#define A_TILE_B   16384                 // 128 rows * 128 bytes
#define B_TILE_B   32768                 // 256 rows * 128 bytes
#define GEMM_SMEM  (NST * (A_TILE_B + B_TILE_B) + 1024)
#define NKT        (D_MODEL / 64)        // 32 k-tiles

struct ProjArgs {
    const __half* A[3];
    const __half* W[3];
    const float*  Bias[3];
    float*        C[3];
};

__global__ __launch_bounds__(256, 1) void gemm_tc(ProjArgs args) {
    extern __shared__ char dyn_smem[];
    char* db = (char*)(((uintptr_t)dyn_smem + 1023) & ~(uintptr_t)1023);
    const uint32_t db_u = smem_u32(db);          // A stages base
    const uint32_t bb_u = db_u + NST * A_TILE_B; // B stages base

    const int z = blockIdx.z;
    const __half* __restrict__ A    = args.A[z];
    const __half* __restrict__ W    = args.W[z];
    const float*  __restrict__ bias = args.Bias[z];
    float* __restrict__        C    = args.C[z];

    const int tid  = threadIdx.x;
    const int lane = tid & 31;
    const int w    = tid >> 5;
    const int wm   = w >> 2;       // 0..1 -> m offset wm*64
    const int wn   = w & 3;        // 0..3 -> n offset wn*64
    const int n0   = blockIdx.x * 256;
    const int m0   = blockIdx.y * 128;

    const __half* Ag = A + (size_t)m0 * D_MODEL;
    const __half* Wg = W + (size_t)n0 * D_MODEL;

    // per-thread load geometry: A = 4 chunks (1024/256), B = 8 chunks (2048/256)
    uint32_t aswo[4], bswo[8];
    size_t   agof[4], bgof[8];
#pragma unroll
    for (int rep = 0; rep < 4; rep++) {
        const int g = rep * 256 + tid;          // 0..1023
        const int r = g >> 3;                   // row 0..127
        const int i = g & 7;                    // 16B chunk
        agof[rep] = (size_t)r * D_MODEL + i * 8;
        aswo[rep] = (uint32_t)((r * 128 + i * 16) ^ ((r & 7) << 4));
    }
#pragma unroll
    for (int rep = 0; rep < 8; rep++) {
        const int g = rep * 256 + tid;          // 0..2047
        const int r = g >> 3;                   // row 0..255
        const int i = g & 7;
        bgof[rep] = (size_t)r * D_MODEL + i * 8;
        bswo[rep] = (uint32_t)((r * 128 + i * 16) ^ ((r & 7) << 4));
    }

    float acc[4][8][4];
#pragma unroll
    for (int i = 0; i < 4; i++)
#pragma unroll
        for (int j = 0; j < 8; j++)
#pragma unroll
            for (int k = 0; k < 4; k++) acc[i][j][k] = 0.f;

    // issue one k-tile stage's loads
    auto issue = [&](int ks) {
        const int slot = ks % NST;
        const int kc   = ks * 64;
        const uint32_t da = db_u + slot * A_TILE_B;
        const uint32_t dbb = bb_u + slot * B_TILE_B;
#pragma unroll
        for (int rep = 0; rep < 4; rep++)
            cp_async16(da + aswo[rep], Ag + agof[rep] + kc);
#pragma unroll
        for (int rep = 0; rep < 8; rep++)
            cp_async16(dbb + bswo[rep], Wg + bgof[rep] + kc);
        CP_COMMIT();
    };

    issue(0);
    issue(1);

    // fragment address bases (lane-dependent, k-independent parts)
    const int m_ = lane >> 3;          // ldsm matrix index 0..3
    const int rr = lane & 7;
    const int a_row_base = wm * 64 + (m_ & 1) * 8 + rr;   // + mf*16
    const int b_row_base = wn * 64 + (m_ & 1) * 8 + rr;   // + nf2*16
    const int k_half     = (m_ >> 1) * 16;                // byte offset: k0-7 vs k8-15

#pragma unroll 1
    for (int kt = 0; kt < NKT; kt++) {
        if (kt < NKT - 2) { CP_WAIT(1); } else { CP_WAIT(0); }
        __syncthreads();
        if (kt + 2 < NKT) issue(kt + 2);

        const int slot = kt % NST;
        const uint32_t da  = db_u + slot * A_TILE_B;
        const uint32_t dbb = bb_u + slot * B_TILE_B;

#pragma unroll
        for (int ks = 0; ks < 4; ks++) {             // 4 x k16 per 64-wide tile
            const int kb = ks * 32 + k_half;         // byte col within 128B row
            uint32_t a[4][4], b[8][2];
#pragma unroll
            for (int mf = 0; mf < 4; mf++) {
                const int row = a_row_base + mf * 16;
                const uint32_t off = (uint32_t)((row * 128 + kb) ^ ((row & 7) << 4));
                ldsm_x4(a[mf], da + off);
            }
#pragma unroll
            for (int nf2 = 0; nf2 < 4; nf2++) {
                const int row = b_row_base + nf2 * 16;
                const uint32_t off = (uint32_t)((row * 128 + kb) ^ ((row & 7) << 4));
                uint32_t t[4];
                ldsm_x4(t, dbb + off);
                b[nf2 * 2][0]     = t[0]; b[nf2 * 2][1]     = t[2];
                b[nf2 * 2 + 1][0] = t[1]; b[nf2 * 2 + 1][1] = t[3];
            }
#pragma unroll
            for (int mf = 0; mf < 4; mf++)
#pragma unroll
                for (int nf = 0; nf < 8; nf++)
                    mma_f16(acc[mf][nf], a[mf], b[nf]);
        }
    }

    // epilogue
#pragma unroll
    for (int mf = 0; mf < 4; mf++) {
#pragma unroll
        for (int nf = 0; nf < 8; nf++) {
            const int row = m0 + wm * 64 + mf * 16 + (lane >> 2);
            const int col = n0 + wn * 64 + nf * 8 + (lane & 3) * 2;
            const float b0 = bias[col], b1 = bias[col + 1];
            float2 v0 = make_float2(acc[mf][nf][0] + b0, acc[mf][nf][1] + b1);
            float2 v1 = make_float2(acc[mf][nf][2] + b0, acc[mf][nf][3] + b1);
            *(float2*)&C[(size_t)row * D_MODEL + col]       = v0;
            *(float2*)&C[(size_t)(row + 8) * D_MODEL + col] = v1;
        }
    }
}

// ---------------------------------------------------------------------------
// Flash attention over the cache only (mask tril(TQ, total) => cols 0..row,
// which always land in the cache half). Causal over [1024 x 1024] per (b,h).
// Block: 128 threads (4 warps), 64 q-rows/block, 64 kv-rows/tile.
// Epilogue writes fp16 (feeds the fp16 O-projection directly).
// ---------------------------------------------------------------------------
#define ATTN_SMEM_BYTES ((2 * 64 * 132 + 64 * 68) * 4)

__global__ __launch_bounds__(128, 2) void attn_kernel(
    const float* __restrict__ gQ,
    const float* __restrict__ cacheK,
    const float* __restrict__ cacheV,
    __half* __restrict__ gO)
{
    extern __shared__ uint32_t sm[];
    uint32_t (*Qs)[132] = (uint32_t(*)[132])sm;                    // 64x132
    uint32_t (*KVs)[132] = (uint32_t(*)[132])(sm + 64 * 132);      // 64x132
    uint32_t (*Ps)[68]  = (uint32_t(*)[68])(sm + 2 * 64 * 132);    // 64x68

    const int tid = threadIdx.x, lane = tid & 31, w = tid >> 5;
    const int qi = blockIdx.x, h = blockIdx.y, b = blockIdx.z;
    const int q0 = qi * 64;

    const float* Qg = gQ     + ((size_t)b * TQ) * D_MODEL + h * HEAD_DIM;
    const float* Kg = cacheK + ((size_t)b * CACHE_LEN) * D_MODEL + h * HEAD_DIM;
    const float* Vg = cacheV + ((size_t)b * CACHE_LEN) * D_MODEL + h * HEAD_DIM;

    // load Q tile (64 x 128)
#pragma unroll
    for (int i = 0; i < 16; i++) {
        const int g = i * 128 + tid;
        const int r = g >> 5, c4 = (g & 31) * 4;
        float4 v = *(const float4*)&Qg[(size_t)(q0 + r) * D_MODEL + c4];
        Qs[r][c4 + 0] = f2tf(v.x);
        Qs[r][c4 + 1] = f2tf(v.y);
        Qs[r][c4 + 2] = f2tf(v.z);
        Qs[r][c4 + 3] = f2tf(v.w);
    }

    float acc_o[16][4];
#pragma unroll
    for (int i = 0; i < 16; i++)
#pragma unroll
        for (int j = 0; j < 4; j++) acc_o[i][j] = 0.f;
    float mrow[2] = {-1e30f, -1e30f};
    float lrow[2] = {0.f, 0.f};
    const float sc = 0.08838834764831845f;   // 1/sqrt(128)

    for (int kt = 0; kt <= qi; kt++) {
        __syncthreads();   // KVs safe to overwrite (and Q visible on iter 0)
        // load K tile
#pragma unroll
        for (int i = 0; i < 16; i++) {
            const int g = i * 128 + tid;
            const int r = g >> 5, c4 = (g & 31) * 4;
            float4 v = *(const float4*)&Kg[(size_t)(kt * 64 + r) * D_MODEL + c4];
            KVs[r][c4 + 0] = f2tf(v.x);
            KVs[r][c4 + 1] = f2tf(v.y);
            KVs[r][c4 + 2] = f2tf(v.z);
            KVs[r][c4 + 3] = f2tf(v.w);
        }
        __syncthreads();

        // S = Q K^T  (warp w owns q rows w*16 .. w*16+15)
        float accs[8][4];
#pragma unroll
        for (int i = 0; i < 8; i++)
#pragma unroll
            for (int j = 0; j < 4; j++) accs[i][j] = 0.f;

#pragma unroll
        for (int ks = 0; ks < 16; ks++) {
            const int kk = ks * 8;
            const int mr = w * 16 + (lane >> 2);
            uint32_t a[4];
            a[0] = Qs[mr    ][kk + (lane & 3)    ];
            a[1] = Qs[mr + 8][kk + (lane & 3)    ];
            a[2] = Qs[mr    ][kk + (lane & 3) + 4];
            a[3] = Qs[mr + 8][kk + (lane & 3) + 4];
#pragma unroll
            for (int nf = 0; nf < 8; nf++) {
                const int nr = nf * 8 + (lane >> 2);
                uint32_t bb[2];
                bb[0] = KVs[nr][kk + (lane & 3)    ];
                bb[1] = KVs[nr][kk + (lane & 3) + 4];
                mma_tf32(accs[nf], a, bb);
            }
        }

        // scale + causal mask (only diagonal tile needs masking)
#pragma unroll
        for (int nf = 0; nf < 8; nf++)
#pragma unroll
            for (int v = 0; v < 4; v++) accs[nf][v] *= sc;
        if (kt == qi) {
#pragma unroll
            for (int nf = 0; nf < 8; nf++)
#pragma unroll
                for (int r = 0; r < 2; r++)
#pragma unroll
                    for (int j = 0; j < 2; j++) {
                        const int cl = nf * 8 + (lane & 3) * 2 + j;
                        const int rl = w * 16 + (lane >> 2) + r * 8;
                        if (cl > rl) accs[nf][r * 2 + j] = -1e30f;
                    }
        }

        // online softmax + write P
#pragma unroll
        for (int r = 0; r < 2; r++) {
            float vmax = -1e30f;
#pragma unroll
            for (int nf = 0; nf < 8; nf++) {
                vmax = fmaxf(vmax, accs[nf][r * 2]);
                vmax = fmaxf(vmax, accs[nf][r * 2 + 1]);
            }
            vmax = fmaxf(vmax, __shfl_xor_sync(0xffffffffu, vmax, 1));
            vmax = fmaxf(vmax, __shfl_xor_sync(0xffffffffu, vmax, 2));
            const float mnew = fmaxf(mrow[r], vmax);
            float psum = 0.f;
            const int qr = w * 16 + (lane >> 2) + r * 8;
#pragma unroll
            for (int nf = 0; nf < 8; nf++)
#pragma unroll
                for (int j = 0; j < 2; j++) {
                    const float p = __expf(accs[nf][r * 2 + j] - mnew);
                    psum += p;
                    Ps[qr][nf * 8 + (lane & 3) * 2 + j] = f2tf(p);
                }
            psum += __shfl_xor_sync(0xffffffffu, psum, 1);
            psum += __shfl_xor_sync(0xffffffffu, psum, 2);
            const float alpha = __expf(mrow[r] - mnew);
            lrow[r] = lrow[r] * alpha + psum;
            mrow[r] = mnew;
#pragma unroll
            for (int nf = 0; nf < 16; nf++) {
                acc_o[nf][r * 2]     *= alpha;
                acc_o[nf][r * 2 + 1] *= alpha;
            }
        }
        __syncwarp();
        __syncthreads();   // all warps done reading K from KVs

        // load V tile into KVs
#pragma unroll
        for (int i = 0; i < 16; i++) {
            const int g = i * 128 + tid;
            const int r = g >> 5, c4 = (g & 31) * 4;
            float4 v = *(const float4*)&Vg[(size_t)(kt * 64 + r) * D_MODEL + c4];
            KVs[r][c4 + 0] = f2tf(v.x);
            KVs[r][c4 + 1] = f2tf(v.y);
            KVs[r][c4 + 2] = f2tf(v.z);
            KVs[r][c4 + 3] = f2tf(v.w);
        }
        __syncthreads();

        // O += P * V
#pragma unroll
        for (int ks = 0; ks < 8; ks++) {
            const int kk = ks * 8;
            const int mr = w * 16 + (lane >> 2);
            uint32_t a[4];
            a[0] = Ps[mr    ][kk + (lane & 3)    ];
            a[1] = Ps[mr + 8][kk + (lane & 3)    ];
            a[2] = Ps[mr    ][kk + (lane & 3) + 4];
            a[3] = Ps[mr + 8][kk + (lane & 3) + 4];
#pragma unroll
            for (int nf = 0; nf < 16; nf++) {
                uint32_t bb[2];
                bb[0] = KVs[kk + (lane & 3)    ][nf * 8 + (lane >> 2)];
                bb[1] = KVs[kk + (lane & 3) + 4][nf * 8 + (lane >> 2)];
                mma_tf32(acc_o[nf], a, bb);
            }
        }
    }

    // normalize + write fp16 (O-proj consumes directly)
#pragma unroll
    for (int nf = 0; nf < 16; nf++)
#pragma unroll
        for (int r = 0; r < 2; r++) {
            const int row = q0 + w * 16 + (lane >> 2) + r * 8;
            const int col = h * HEAD_DIM + nf * 8 + (lane & 3) * 2;
            const float inv = 1.f / lrow[r];
            __half2 hv = __floats2half2_rn(acc_o[nf][r * 2] * inv,
                                           acc_o[nf][r * 2 + 1] * inv);
            *(__half2*)&gO[((size_t)b * TQ + row) * D_MODEL + col] = hv;
        }
}

// ---------------------------------------------------------------------------
// new_k / new_v: permutation copy of (cache ++ projected) head-split reshape.
// dst[b][j][c] with h=j>>7, t=(j&127)*16+(c>>7), d=c&127; t<1024 -> cache.
// ---------------------------------------------------------------------------
__global__ __launch_bounds__(256) void copy_newkv(
    const float* __restrict__ cache,
    const float* __restrict__ proj,
    float* __restrict__ dst)
{
    const int i = blockIdx.x * 256 + threadIdx.x;  // float4 index, 4*2048*512 total
    const int b   = i >> 20;
    const int rem = i & 1048575;
    const int j   = rem >> 9;
    const int c   = (rem & 511) * 4;
    const int h   = j >> 7;
    const int t   = ((j & 127) << 4) + (c >> 7);
    const int d   = c & 127;

    const float* src = (t < CACHE_LEN)
        ? cache + (((size_t)b * CACHE_LEN + t) * D_MODEL + h * HEAD_DIM + d)
        : proj  + (((size_t)b * TQ + (t - CACHE_LEN)) * D_MODEL + h * HEAD_DIM + d);
    float4 v = *(const float4*)src;
    *(float4*)&dst[((size_t)b * 2048 + j) * D_MODEL + c] = v;
}

// ---------------------------------------------------------------------------
// launch
// ---------------------------------------------------------------------------
extern "C" void kernel_launch(void* const* d_in, const int* in_sizes, int n_in,
                              void* d_out, int out_size)
{
    const float* query   = (const float*)d_in[0];
    const float* key     = (const float*)d_in[1];
    const float* value   = (const float*)d_in[2];
    const float* cacheK  = (const float*)d_in[3];
    const float* cacheV  = (const float*)d_in[4];
    const float* Wq      = (const float*)d_in[5];
    const float* bq      = (const float*)d_in[6];
    const float* Wk      = (const float*)d_in[7];
    const float* bk      = (const float*)d_in[8];
    const float* Wv      = (const float*)d_in[9];
    const float* bv      = (const float*)d_in[10];
    const float* Wo      = (const float*)d_in[11];
    const float* bo      = (const float*)d_in[12];
    float* out = (float*)d_out;

    float *pQ, *pK, *pV;
    __half *pO, *phq, *phk, *phv, *phWq, *phWk, *phWv, *phWo;
    cudaGetSymbolAddress((void**)&pQ, g_Q);
    cudaGetSymbolAddress((void**)&pK, g_K);
    cudaGetSymbolAddress((void**)&pV, g_V);
    cudaGetSymbolAddress((void**)&pO, g_O);
    cudaGetSymbolAddress((void**)&phq, g_hq);
    cudaGetSymbolAddress((void**)&phk, g_hk);
    cudaGetSymbolAddress((void**)&phv, g_hv);
    cudaGetSymbolAddress((void**)&phWq, g_hWq);
    cudaGetSymbolAddress((void**)&phWk, g_hWk);
    cudaGetSymbolAddress((void**)&phWv, g_hWv);
    cudaGetSymbolAddress((void**)&phWo, g_hWo);

    // 1) pre-round inputs to fp16
    RoundArgs ra;
    ra.src[0] = query; ra.dst[0] = phq;  ra.n4[0] = M_ROWS * D_MODEL / 4;
    ra.src[1] = key;   ra.dst[1] = phk;  ra.n4[1] = M_ROWS * D_MODEL / 4;
    ra.src[2] = value; ra.dst[2] = phv;  ra.n4[2] = M_ROWS * D_MODEL / 4;
    ra.src[3] = Wq;    ra.dst[3] = phWq; ra.n4[3] = D_MODEL * D_MODEL / 4;
    ra.src[4] = Wk;    ra.dst[4] = phWk; ra.n4[4] = D_MODEL * D_MODEL / 4;
    ra.src[5] = Wv;    ra.dst[5] = phWv; ra.n4[5] = D_MODEL * D_MODEL / 4;
    ra.src[6] = Wo;    ra.dst[6] = phWo; ra.n4[6] = D_MODEL * D_MODEL / 4;
    round_f16<<<dim3(M_ROWS * D_MODEL / 4 / 256, 1, 7), 256>>>(ra);

    cudaFuncSetAttribute(gemm_tc, cudaFuncAttributeMaxDynamicSharedMemorySize,
                         GEMM_SMEM);

    // 2) Q/K/V projections (fp16 HMMA, 128x256 CTA tiles)
    ProjArgs pa;
    pa.A[0] = phq;  pa.A[1] = phk;  pa.A[2] = phv;
    pa.W[0] = phWq; pa.W[1] = phWk; pa.W[2] = phWv;
    pa.Bias[0] = bq; pa.Bias[1] = bk; pa.Bias[2] = bv;
    pa.C[0] = pQ;    pa.C[1] = pK;  pa.C[2] = pV;
    gemm_tc<<<dim3(D_MODEL / 256, M_ROWS / 128, 3), 256, GEMM_SMEM>>>(pa);

    // 3) attention (cache-only, causal) — tf32, writes fp16
    cudaFuncSetAttribute(attn_kernel, cudaFuncAttributeMaxDynamicSharedMemorySize,
                         ATTN_SMEM_BYTES);
    attn_kernel<<<dim3(TQ / 64, NUM_HEADS, BATCH), 128, ATTN_SMEM_BYTES>>>(
        pQ, cacheK, cacheV, pO);

    // 4) output projection -> out[0 .. 8388608)
    ProjArgs po;
    po.A[0] = pO; po.W[0] = phWo; po.Bias[0] = bo; po.C[0] = out;
    po.A[1] = pO; po.W[1] = phWo; po.Bias[1] = bo; po.C[1] = out;
    po.A[2] = pO; po.W[2] = phWo; po.Bias[2] = bo; po.C[2] = out;
    gemm_tc<<<dim3(D_MODEL / 256, M_ROWS / 128, 1), 256, GEMM_SMEM>>>(po);

    // 5) new_k / new_v
    const int nf4 = BATCH * 2048 * (D_MODEL / 4);   // 4194304 float4s
    copy_newkv<<<nf4 / 256, 256>>>(cacheK, pK, out + 8388608);
    copy_newkv<<<nf4 / 256, 256>>>(cacheV, pV, out + 25165824);
}

// round 6
// speedup vs baseline: 1.3810x; 1.3810x over previous
#include <cuda_runtime.h>
#include <cuda_bf16.h>
#include <cuda_fp16.h>
#include <cstdint>
#include <cstdio>

// ---------------------------------------------------------------------------
// Problem constants
// ---------------------------------------------------------------------------
#define D_MODEL   2048
#define NUM_HEADS 16
#define HEAD_DIM  128
#define BATCH     4
#define TQ        1024
#define CACHE_LEN 1024
#define M_ROWS    (BATCH * TQ)          // 4096

// scratch (device globals: allocation-free scratch per harness rules)
__device__ __half g_hQ[M_ROWS * D_MODEL];             // projected Q, fp16
__device__ __half g_O[M_ROWS * D_MODEL];              // attention out, fp16
// fp16 pre-rounded inputs
__device__ __half g_hq[M_ROWS * D_MODEL];
__device__ __half g_hk[M_ROWS * D_MODEL];
__device__ __half g_hv[M_ROWS * D_MODEL];
__device__ __half g_hWq[D_MODEL * D_MODEL];
__device__ __half g_hWk[D_MODEL * D_MODEL];
__device__ __half g_hWv[D_MODEL * D_MODEL];
__device__ __half g_hWo[D_MODEL * D_MODEL];
__device__ __half g_hck[BATCH * CACHE_LEN * D_MODEL]; // fp16 cache K (attention)
__device__ __half g_hcv[BATCH * CACHE_LEN * D_MODEL]; // fp16 cache V (attention)

// ---------------------------------------------------------------------------
// helpers
// ---------------------------------------------------------------------------
__device__ __forceinline__ uint32_t smem_u32(const void* p) {
    uint32_t a;
    asm("{ .reg .u64 t; cvta.to.shared.u64 t, %1; cvt.u32.u64 %0, t; }"
        : "=r"(a) : "l"(p));
    return a;
}

// fp16 m16n8k16: D += A*B  (row.col, f32 accum)
__device__ __forceinline__ void mma_f16(float* d, const uint32_t* a, const uint32_t* b) {
    asm volatile(
        "mma.sync.aligned.m16n8k16.row.col.f32.f16.f16.f32 "
        "{%0,%1,%2,%3}, {%4,%5,%6,%7}, {%8,%9}, {%0,%1,%2,%3};\n"
        : "+f"(d[0]), "+f"(d[1]), "+f"(d[2]), "+f"(d[3])
        : "r"(a[0]), "r"(a[1]), "r"(a[2]), "r"(a[3]),
          "r"(b[0]), "r"(b[1]));
}

__device__ __forceinline__ void ldsm_x4(uint32_t* r, uint32_t addr) {
    asm volatile("ldmatrix.sync.aligned.m8n8.x4.shared.b16 {%0,%1,%2,%3}, [%4];"
                 : "=r"(r[0]), "=r"(r[1]), "=r"(r[2]), "=r"(r[3]) : "r"(addr));
}

__device__ __forceinline__ void ldsm_x4t(uint32_t* r, uint32_t addr) {
    asm volatile("ldmatrix.sync.aligned.m8n8.x4.trans.shared.b16 {%0,%1,%2,%3}, [%4];"
                 : "=r"(r[0]), "=r"(r[1]), "=r"(r[2]), "=r"(r[3]) : "r"(addr));
}

__device__ __forceinline__ void cp_async16(uint32_t dst, const void* src) {
    asm volatile("cp.async.cg.shared.global [%0], [%1], 16;"
                 :: "r"(dst), "l"(src));
}
#define CP_COMMIT()  asm volatile("cp.async.commit_group;" ::: "memory")
#define CP_WAIT(N)   asm volatile("cp.async.wait_group %0;" :: "n"(N) : "memory")

// ---------------------------------------------------------------------------
// pre-rounding pass: dst = fp16(src) for 9 tensors in one launch (grid.z)
// ---------------------------------------------------------------------------
struct RoundArgs {
    const float* src[9];
    __half*      dst[9];
    int          n4[9];     // number of float4 elements
};

__global__ __launch_bounds__(256) void round_f16(RoundArgs ra) {
    const int z = blockIdx.z;
    const int i = blockIdx.x * 256 + threadIdx.x;
    if (i >= ra.n4[z]) return;
    float4 v = ((const float4*)ra.src[z])[i];
    __half2 h0 = __floats2half2_rn(v.x, v.y);
    __half2 h1 = __floats2half2_rn(v.z, v.w);
    uint2 u;
    u.x = *(uint32_t*)&h0;
    u.y = *(uint32_t*)&h1;
    ((uint2*)ra.dst[z])[i] = u;
}

// ---------------------------------------------------------------------------
// Pipelined TN GEMM (fp16 HMMA):  C[M,N] = A[M,K] * W[N,K]^T + bias[N]
// R4 tiling: CTA 128x128, warp 64x32 (8 warps 2x4), K-tile 64, 3-stage
// cp.async ring, ldmatrix frags, m16n8k16 HMMA, fp32 accum + bias.
// Output modes: 0 = fp16 to Ch (Q-proj), 1 = permuted fp32 into new_kv
// (K/V proj land directly in d_out), 2 = plain fp32 (O-proj).
// ---------------------------------------------------------------------------
#define NST        3
#define TILE_B     16384                 // 128 rows * 128 bytes
#define GEMM_SMEM  (2 * NST * TILE_B + 1024)
#define NKT        (D_MODEL / 64)        // 32 k-tiles

struct ProjArgs {
    const __half* A[3];
    const __half* W[3];
    const float*  Bias[3];
    float*        C[3];
    __half*       Ch[3];
    int           mode[3];
};

__global__ __launch_bounds__(256, 2) void gemm_tc(ProjArgs args) {
    extern __shared__ char dyn_smem[];
    char* db = (char*)(((uintptr_t)dyn_smem + 1023) & ~(uintptr_t)1023);
    const uint32_t db_u = smem_u32(db);

    const int z = blockIdx.z;
    const __half* __restrict__ A    = args.A[z];
    const __half* __restrict__ W    = args.W[z];
    const float*  __restrict__ bias = args.Bias[z];
    float* __restrict__        C    = args.C[z];
    __half* __restrict__       Ch   = args.Ch[z];
    const int mode = args.mode[z];

    const int tid  = threadIdx.x;
    const int lane = tid & 31;
    const int w    = tid >> 5;
    const int wm   = w >> 2;       // 0..1
    const int wn   = w & 3;        // 0..3
    const int n0   = blockIdx.x * 128;
    const int m0   = blockIdx.y * 128;

    const __half* Ag = A + (size_t)m0 * D_MODEL;
    const __half* Wg = W + (size_t)n0 * D_MODEL;

    uint32_t swoff[4];
    size_t   gofs[4];
#pragma unroll
    for (int rep = 0; rep < 4; rep++) {
        const int g = rep * 256 + tid;          // 0..1023
        const int r = g >> 3;                   // row 0..127
        const int i = g & 7;                    // 16B chunk
        gofs[rep]  = (size_t)r * D_MODEL + i * 8;
        swoff[rep] = (uint32_t)((r * 128 + i * 16) ^ ((r & 7) << 4));
    }

    float acc[4][4][4];
#pragma unroll
    for (int i = 0; i < 4; i++)
#pragma unroll
        for (int j = 0; j < 4; j++)
#pragma unroll
            for (int k = 0; k < 4; k++) acc[i][j][k] = 0.f;

    auto issue = [&](int ks) {
        const int slot = ks % NST;
        const int kc   = ks * 64;
        const uint32_t da  = db_u + slot * TILE_B;
        const uint32_t dbb = db_u + NST * TILE_B + slot * TILE_B;
#pragma unroll
        for (int rep = 0; rep < 4; rep++)
            cp_async16(da + swoff[rep], Ag + gofs[rep] + kc);
#pragma unroll
        for (int rep = 0; rep < 4; rep++)
            cp_async16(dbb + swoff[rep], Wg + gofs[rep] + kc);
        CP_COMMIT();
    };

    issue(0);
    issue(1);

    const int m_ = lane >> 3;
    const int rr = lane & 7;
    const int a_row_base = wm * 64 + (m_ & 1) * 8 + rr;
    const int b_row_base = wn * 32 + (m_ & 1) * 8 + rr;
    const int k_half     = (m_ >> 1) * 16;

#pragma unroll 1
    for (int kt = 0; kt < NKT; kt++) {
        if (kt < NKT - 2) { CP_WAIT(1); } else { CP_WAIT(0); }
        __syncthreads();
        if (kt + 2 < NKT) issue(kt + 2);

        const int slot = kt % NST;
        const uint32_t da  = db_u + slot * TILE_B;
        const uint32_t dbb = db_u + NST * TILE_B + slot * TILE_B;

#pragma unroll
        for (int ks = 0; ks < 4; ks++) {
            const int kb = ks * 32 + k_half;
            uint32_t a[4][4], b[4][2];
#pragma unroll
            for (int mf = 0; mf < 4; mf++) {
                const int row = a_row_base + mf * 16;
                const uint32_t off = (uint32_t)((row * 128 + kb) ^ ((row & 7) << 4));
                ldsm_x4(a[mf], da + off);
            }
#pragma unroll
            for (int nf2 = 0; nf2 < 2; nf2++) {
                const int row = b_row_base + nf2 * 16;
                const uint32_t off = (uint32_t)((row * 128 + kb) ^ ((row & 7) << 4));
                uint32_t t[4];
                ldsm_x4(t, dbb + off);
                b[nf2 * 2][0]     = t[0]; b[nf2 * 2][1]     = t[2];
                b[nf2 * 2 + 1][0] = t[1]; b[nf2 * 2 + 1][1] = t[3];
            }
#pragma unroll
            for (int mf = 0; mf < 4; mf++)
#pragma unroll
                for (int nf = 0; nf < 4; nf++)
                    mma_f16(acc[mf][nf], a[mf], b[nf]);
        }
    }

    // epilogue (per mode)
#pragma unroll
    for (int mf = 0; mf < 4; mf++) {
#pragma unroll
        for (int nf = 0; nf < 4; nf++) {
            const int row = m0 + wm * 64 + mf * 16 + (lane >> 2);
            const int col = n0 + wn * 32 + nf * 8 + (lane & 3) * 2;
            const float b0 = bias[col], b1 = bias[col + 1];
            const float x0 = acc[mf][nf][0] + b0, x1 = acc[mf][nf][1] + b1;
            const float y0 = acc[mf][nf][2] + b0, y1 = acc[mf][nf][3] + b1;
            if (mode == 0) {
                __half2 h0 = __floats2half2_rn(x0, x1);
                __half2 h1 = __floats2half2_rn(y0, y1);
                *(__half2*)&Ch[(size_t)row * D_MODEL + col]       = h0;
                *(__half2*)&Ch[(size_t)(row + 8) * D_MODEL + col] = h1;
            } else if (mode == 1) {
                // direct write into new_k/new_v (proj half): t' = 1024 + t
                const int h  = col >> 7, d = col & 127;
#pragma unroll
                for (int rep = 0; rep < 2; rep++) {
                    const int rw = row + rep * 8;
                    const int bb = rw >> 10, t = rw & 1023;
                    const int j  = h * 128 + 64 + (t >> 4);
                    const int c  = (t & 15) * 128 + d;
                    float2 v = rep ? make_float2(y0, y1) : make_float2(x0, x1);
                    *(float2*)&C[((size_t)bb * 2048 + j) * 2048 + c] = v;
                }
            } else {
                *(float2*)&C[(size_t)row * D_MODEL + col]       = make_float2(x0, x1);
                *(float2*)&C[(size_t)(row + 8) * D_MODEL + col] = make_float2(y0, y1);
            }
        }
    }
}

// ---------------------------------------------------------------------------
// fp16 flash attention over the cache only (mask tril(TQ,total) => cache half).
// 128 threads (4 warps), 64 q-rows/CTA, 64 kv/tile, K/V double-buffered via
// cp.async. m16n8k16 HMMA; V fragments via ldmatrix.trans.
// SMEM: Q 16K | K0 K1 32K | V0 V1 32K | P 8K  = 88K, 2 CTA/SM.
// ---------------------------------------------------------------------------
#define QOFF 0
#define KOFF 16384
#define VOFF (KOFF + 2 * 16384)
#define POFF (VOFF + 2 * 16384)
#define ATT_SMEM (POFF + 8192)   // 90112

__global__ __launch_bounds__(128, 2) void attn_kernel(
    const __half* __restrict__ gQ,
    const __half* __restrict__ hK,
    const __half* __restrict__ hV,
    __half* __restrict__ gO)
{
    extern __shared__ char smc[];
    const uint32_t sb = smem_u32(smc);
    const int tid = threadIdx.x, lane = tid & 31, w = tid >> 5;
    const int qi = blockIdx.x, h = blockIdx.y, b = blockIdx.z;
    const int q0 = qi * 64;

    const __half* Qg = gQ + ((size_t)b * TQ + q0) * D_MODEL + h * HEAD_DIM;
    const __half* Kg = hK + (size_t)b * CACHE_LEN * D_MODEL + h * HEAD_DIM;
    const __half* Vg = hV + (size_t)b * CACHE_LEN * D_MODEL + h * HEAD_DIM;

    // Q tile 64x128 halves -> swizzled smem (rows 256B)
#pragma unroll
    for (int rep = 0; rep < 8; rep++) {
        const int g = rep * 128 + tid;
        const int r = g >> 4, i = g & 15;
        uint4 v = *(const uint4*)(Qg + (size_t)r * D_MODEL + i * 8);
        *(uint4*)(smc + QOFF + ((r * 256 + i * 16) ^ ((r & 7) << 4))) = v;
    }

    auto issueK = [&](int kt) {
#pragma unroll
        for (int rep = 0; rep < 8; rep++) {
            const int g = rep * 128 + tid;
            const int r = g >> 4, i = g & 15;
            cp_async16(sb + KOFF + (kt & 1) * 16384 + ((r * 256 + i * 16) ^ ((r & 7) << 4)),
                       Kg + (size_t)(kt * 64 + r) * D_MODEL + i * 8);
        }
        CP_COMMIT();
    };
    auto issueV = [&](int kt) {
#pragma unroll
        for (int rep = 0; rep < 8; rep++) {
            const int g = rep * 128 + tid;
            const int r = g >> 4, i = g & 15;
            cp_async16(sb + VOFF + (kt & 1) * 16384 + ((r * 256 + i * 16) ^ ((r & 7) << 4)),
                       Vg + (size_t)(kt * 64 + r) * D_MODEL + i * 8);
        }
        CP_COMMIT();
    };

    issueK(0); issueV(0);
    if (qi >= 1) { issueK(1); issueV(1); } else { CP_COMMIT(); CP_COMMIT(); }

    float acc_o[16][4];
#pragma unroll
    for (int i = 0; i < 16; i++)
#pragma unroll
        for (int j = 0; j < 4; j++) acc_o[i][j] = 0.f;
    float mrow[2] = {-1e30f, -1e30f};
    float lrow[2] = {0.f, 0.f};
    const float sc = 0.08838834764831845f;   // 1/sqrt(128)

    const int m_ = lane >> 3, rr = lane & 7;
    const int kh    = (m_ >> 1) * 16;
    const int a_row = w * 16 + (m_ & 1) * 8 + rr;

    for (int kt = 0; kt <= qi; kt++) {
        CP_WAIT(3);            // K(kt) landed (per-thread)
        __syncthreads();       // all threads' chunks visible (also covers Q on kt=0)

        const uint32_t kbase = sb + KOFF + (kt & 1) * 16384;
        float accs[8][4];
#pragma unroll
        for (int i = 0; i < 8; i++)
#pragma unroll
            for (int j = 0; j < 4; j++) accs[i][j] = 0.f;

#pragma unroll
        for (int ks = 0; ks < 8; ks++) {            // 8 x k16 over headdim 128
            const int colb = ks * 32 + kh;
            uint32_t a[4];
            ldsm_x4(a, sb + QOFF + ((a_row * 256 + colb) ^ ((a_row & 7) << 4)));
            uint32_t bfr[8][2];
#pragma unroll
            for (int nf2 = 0; nf2 < 4; nf2++) {
                const int row = nf2 * 16 + (m_ & 1) * 8 + rr;   // kv rows 0..63
                uint32_t t[4];
                ldsm_x4(t, kbase + ((row * 256 + colb) ^ ((row & 7) << 4)));
                bfr[nf2 * 2][0]     = t[0]; bfr[nf2 * 2][1]     = t[2];
                bfr[nf2 * 2 + 1][0] = t[1]; bfr[nf2 * 2 + 1][1] = t[3];
            }
#pragma unroll
            for (int nf = 0; nf < 8; nf++) mma_f16(accs[nf], a, bfr[nf]);
        }

        // scale + causal mask (diagonal tile only)
#pragma unroll
        for (int nf = 0; nf < 8; nf++)
#pragma unroll
            for (int v = 0; v < 4; v++) accs[nf][v] *= sc;
        if (kt == qi) {
#pragma unroll
            for (int nf = 0; nf < 8; nf++)
#pragma unroll
                for (int r = 0; r < 2; r++)
#pragma unroll
                    for (int j = 0; j < 2; j++) {
                        const int cl = nf * 8 + (lane & 3) * 2 + j;
                        const int rl = w * 16 + (lane >> 2) + r * 8;
                        if (cl > rl) accs[nf][r * 2 + j] = -1e30f;
                    }
        }

        // online softmax + write P (fp16, swizzled)
#pragma unroll
        for (int r = 0; r < 2; r++) {
            float vmax = -1e30f;
#pragma unroll
            for (int nf = 0; nf < 8; nf++) {
                vmax = fmaxf(vmax, accs[nf][r * 2]);
                vmax = fmaxf(vmax, accs[nf][r * 2 + 1]);
            }
            vmax = fmaxf(vmax, __shfl_xor_sync(0xffffffffu, vmax, 1));
            vmax = fmaxf(vmax, __shfl_xor_sync(0xffffffffu, vmax, 2));
            const float mnew = fmaxf(mrow[r], vmax);
            float psum = 0.f;
            const int qr = w * 16 + (lane >> 2) + r * 8;
#pragma unroll
            for (int nf = 0; nf < 8; nf++) {
                const float p0 = __expf(accs[nf][r * 2]     - mnew);
                const float p1 = __expf(accs[nf][r * 2 + 1] - mnew);
                psum += p0 + p1;
                __half2 hp = __floats2half2_rn(p0, p1);
                const uint32_t boff = (uint32_t)(qr * 128 + nf * 16 + (lane & 3) * 4)
                                      ^ ((qr & 7) << 4);
                *(uint32_t*)(smc + POFF + boff) = *(uint32_t*)&hp;
            }
            psum += __shfl_xor_sync(0xffffffffu, psum, 1);
            psum += __shfl_xor_sync(0xffffffffu, psum, 2);
            const float alpha = __expf(mrow[r] - mnew);
            lrow[r] = lrow[r] * alpha + psum;
            mrow[r] = mnew;
#pragma unroll
            for (int nf = 0; nf < 16; nf++) {
                acc_o[nf][r * 2]     *= alpha;
                acc_o[nf][r * 2 + 1] *= alpha;
            }
        }

        CP_WAIT(2);            // V(kt) landed
        __syncthreads();       // ... and visible; all warps done reading K(kt)
        if (kt + 2 <= qi) issueK(kt + 2); else CP_COMMIT();

        // O += P * V  (P from swizzled fp16 smem, V frags via ldmatrix.trans)
        const uint32_t vbase = sb + VOFF + (kt & 1) * 16384;
        const int p_row = w * 16 + (m_ & 1) * 8 + rr;
        const int vr_lane = ((lane >> 3) & 1) * 8 + (lane & 7);
        const int vc_lane = (lane >> 4) * 16;
#pragma unroll
        for (int ks = 0; ks < 4; ks++) {            // 4 x k16 over 64 kv
            const int colb = ks * 32 + kh;
            uint32_t aP[4];
            ldsm_x4(aP, sb + POFF + ((p_row * 128 + colb) ^ ((p_row & 7) << 4)));
#pragma unroll
            for (int dg = 0; dg < 8; dg++) {        // 16 halves of headdim each
                const int vrow = ks * 16 + vr_lane;
                const int vcol = dg * 32 + vc_lane;
                uint32_t t[4];
                ldsm_x4t(t, vbase + ((vrow * 256 + vcol) ^ ((vrow & 7) << 4)));
                uint32_t b0[2] = { t[0], t[1] };
                uint32_t b1[2] = { t[2], t[3] };
                mma_f16(acc_o[dg * 2],     aP, b0);
                mma_f16(acc_o[dg * 2 + 1], aP, b1);
            }
        }
        __syncthreads();       // all warps done reading V(kt)
        if (kt + 2 <= qi) issueV(kt + 2); else CP_COMMIT();
    }

    // normalize + write fp16
#pragma unroll
    for (int nf = 0; nf < 16; nf++)
#pragma unroll
        for (int r = 0; r < 2; r++) {
            const int row = q0 + w * 16 + (lane >> 2) + r * 8;
            const int col = h * HEAD_DIM + nf * 8 + (lane & 3) * 2;
            const float inv = 1.f / lrow[r];
            __half2 hv = __floats2half2_rn(acc_o[nf][r * 2] * inv,
                                           acc_o[nf][r * 2 + 1] * inv);
            *(__half2*)&gO[((size_t)b * TQ + row) * D_MODEL + col] = hv;
        }
}

// ---------------------------------------------------------------------------
// new_k / new_v cache halves only (proj halves written by the K/V GEMM).
// grid.z: 0 -> K, 1 -> V. 2097152 float4 per tensor.
// ---------------------------------------------------------------------------
__global__ __launch_bounds__(256) void copy_cache_kv(
    const float* __restrict__ cacheK,
    const float* __restrict__ cacheV,
    float* __restrict__ dstK,
    float* __restrict__ dstV)
{
    const int i = blockIdx.x * 256 + threadIdx.x;
    const int b   = i >> 19;            // 524288 float4 per batch
    const int rem = i & 524287;
    const int jj  = rem >> 9;           // 0..1023 (h*64 + cache row)
    const int c   = (rem & 511) * 4;
    const int h   = jj >> 6;
    const int j   = h * 128 + (jj & 63);
    const int t   = (jj & 63) * 16 + (c >> 7);
    const int d   = c & 127;

    const float* cache = blockIdx.z ? cacheV : cacheK;
    float*       dst   = blockIdx.z ? dstV   : dstK;
    float4 v = *(const float4*)&cache[((size_t)b * CACHE_LEN + t) * D_MODEL + h * HEAD_DIM + d];
    *(float4*)&dst[((size_t)b * 2048 + j) * D_MODEL + c] = v;
}

// ---------------------------------------------------------------------------
// launch
// ---------------------------------------------------------------------------
extern "C" void kernel_launch(void* const* d_in, const int* in_sizes, int n_in,
                              void* d_out, int out_size)
{
    const float* query   = (const float*)d_in[0];
    const float* key     = (const float*)d_in[1];
    const float* value   = (const float*)d_in[2];
    const float* cacheK  = (const float*)d_in[3];
    const float* cacheV  = (const float*)d_in[4];
    const float* Wq      = (const float*)d_in[5];
    const float* bq      = (const float*)d_in[6];
    const float* Wk      = (const float*)d_in[7];
    const float* bk      = (const float*)d_in[8];
    const float* Wv      = (const float*)d_in[9];
    const float* bv      = (const float*)d_in[10];
    const float* Wo      = (const float*)d_in[11];
    const float* bo      = (const float*)d_in[12];
    float* out = (float*)d_out;

    __half *phQ, *pO, *phq, *phk, *phv, *phWq, *phWk, *phWv, *phWo, *phck, *phcv;
    cudaGetSymbolAddress((void**)&phQ, g_hQ);
    cudaGetSymbolAddress((void**)&pO, g_O);
    cudaGetSymbolAddress((void**)&phq, g_hq);
    cudaGetSymbolAddress((void**)&phk, g_hk);
    cudaGetSymbolAddress((void**)&phv, g_hv);
    cudaGetSymbolAddress((void**)&phWq, g_hWq);
    cudaGetSymbolAddress((void**)&phWk, g_hWk);
    cudaGetSymbolAddress((void**)&phWv, g_hWv);
    cudaGetSymbolAddress((void**)&phWo, g_hWo);
    cudaGetSymbolAddress((void**)&phck, g_hck);
    cudaGetSymbolAddress((void**)&phcv, g_hcv);

    // 1) pre-round inputs (+ caches for attention) to fp16
    const int NA = M_ROWS * D_MODEL / 4;     // 2097152
    const int NW = D_MODEL * D_MODEL / 4;    // 1048576
    RoundArgs ra;
    ra.src[0] = query;  ra.dst[0] = phq;  ra.n4[0] = NA;
    ra.src[1] = key;    ra.dst[1] = phk;  ra.n4[1] = NA;
    ra.src[2] = value;  ra.dst[2] = phv;  ra.n4[2] = NA;
    ra.src[3] = Wq;     ra.dst[3] = phWq; ra.n4[3] = NW;
    ra.src[4] = Wk;     ra.dst[4] = phWk; ra.n4[4] = NW;
    ra.src[5] = Wv;     ra.dst[5] = phWv; ra.n4[5] = NW;
    ra.src[6] = Wo;     ra.dst[6] = phWo; ra.n4[6] = NW;
    ra.src[7] = cacheK; ra.dst[7] = phck; ra.n4[7] = NA;
    ra.src[8] = cacheV; ra.dst[8] = phcv; ra.n4[8] = NA;
    round_f16<<<dim3(NA / 256, 1, 9), 256>>>(ra);

    // 2) new_k / new_v cache halves (independent of everything else)
    copy_cache_kv<<<dim3(2097152 / 256, 1, 2), 256>>>(
        cacheK, cacheV, out + 8388608, out + 25165824);

    cudaFuncSetAttribute(gemm_tc, cudaFuncAttributeMaxDynamicSharedMemorySize,
                         GEMM_SMEM);

    // 3) Q/K/V projections. Q -> fp16 scratch; K/V -> straight into d_out.
    ProjArgs pa;
    pa.A[0] = phq;  pa.W[0] = phWq; pa.Bias[0] = bq;
    pa.A[1] = phk;  pa.W[1] = phWk; pa.Bias[1] = bk;
    pa.A[2] = phv;  pa.W[2] = phWv; pa.Bias[2] = bv;
    pa.Ch[0] = phQ; pa.C[0] = nullptr;          pa.mode[0] = 0;
    pa.Ch[1] = nullptr; pa.C[1] = out + 8388608;  pa.mode[1] = 1;
    pa.Ch[2] = nullptr; pa.C[2] = out + 25165824; pa.mode[2] = 1;
    gemm_tc<<<dim3(D_MODEL / 128, M_ROWS / 128, 3), 256, GEMM_SMEM>>>(pa);

    // 4) attention (cache-only, causal), fp16 HMMA
    cudaFuncSetAttribute(attn_kernel, cudaFuncAttributeMaxDynamicSharedMemorySize,
                         ATT_SMEM);
    attn_kernel<<<dim3(TQ / 64, NUM_HEADS, BATCH), 128, ATT_SMEM>>>(
        phQ, phck, phcv, pO);

    // 5) output projection -> out[0 .. 8388608)
    ProjArgs po;
    po.A[0] = pO; po.W[0] = phWo; po.Bias[0] = bo;
    po.C[0] = out; po.Ch[0] = nullptr; po.mode[0] = 2;
    po.A[1] = po.A[0]; po.W[1] = po.W[0]; po.Bias[1] = po.Bias[0];
    po.C[1] = po.C[0]; po.Ch[1] = nullptr; po.mode[1] = 2;
    po.A[2] = po.A[0]; po.W[2] = po.W[0]; po.Bias[2] = po.Bias[0];
    po.C[2] = po.C[0]; po.Ch[2] = nullptr; po.mode[2] = 2;
    gemm_tc<<<dim3(D_MODEL / 128, M_ROWS / 128, 1), 256, GEMM_SMEM>>>(po);
}